// round 3
// baseline (speedup 1.0000x reference)
#include <cuda_runtime.h>
#include <cstdint>

#define BB 16
#define NN 25200
#define NCLS 80
#define PSTR 85
#define MAX_DET 300
#define M_TGT 50
#define CONF_THRES 0.8f
#define NMS_THRES 0.4f
#define CAND_MAX 12288
#define NBINS 512
#define SURV_MAX 2048
#define KW 10   // ceil(300/32) words

// ---- global scratch (no allocation allowed) ----
__device__ int      g_cand_count[BB];
__device__ int      g_hist[BB][NBINS];
__device__ float    g_cand_score[BB][CAND_MAX];
__device__ unsigned g_cand_meta[BB][CAND_MAX];

__device__ __forceinline__ int score_bin(float sc) {
    int b = (int)((sc - CONF_THRES) * (NBINS / 0.2f));
    if (b < 0) b = 0;
    if (b >= NBINS) b = NBINS - 1;
    return b;
}

// ---- Kernel A: warp per anchor: score = obj * max(cls), argmax (lowest idx on tie) ----
__global__ void __launch_bounds__(256) score_kernel(const float* __restrict__ preds) {
    int gwarp = (blockIdx.x * blockDim.x + threadIdx.x) >> 5;
    int lane  = threadIdx.x & 31;
    if (gwarp >= BB * NN) return;   // warp-uniform exit (grid divides exactly)
    int b = gwarp / NN;
    int n = gwarp - b * NN;
    const float* p = preds + (size_t)gwarp * PSTR;

    float obj = __ldg(p + 4);
    float v0 = __ldg(p + 5 + lane);            // classes  0..31
    float v1 = __ldg(p + 5 + 32 + lane);       // classes 32..63
    float v2 = (lane < NCLS - 64) ? __ldg(p + 5 + 64 + lane) : -1.0f; // 64..79

    float best = v0; int bi = lane;
    if (v1 > best) { best = v1; bi = lane + 32; }
    if (v2 > best) { best = v2; bi = lane + 64; }

    #pragma unroll
    for (int off = 16; off > 0; off >>= 1) {
        float ov = __shfl_down_sync(0xFFFFFFFFu, best, off);
        int   oi = __shfl_down_sync(0xFFFFFFFFu, bi, off);
        if (ov > best || (ov == best && oi < bi)) { best = ov; bi = oi; }
    }

    if (lane == 0) {
        float score = obj * best;
        if (score > CONF_THRES) {
            int pos = atomicAdd(&g_cand_count[b], 1);
            if (pos < CAND_MAX) {
                g_cand_score[b][pos] = score;
                g_cand_meta[b][pos]  = (unsigned)n | ((unsigned)bi << 16);
            }
            atomicAdd(&g_hist[b][score_bin(score)], 1);
        }
    }
}

// ---- Kernel B: per-batch top-300 + NMS + targets + output ----
__global__ void __launch_bounds__(512) select_nms_kernel(
    const float* __restrict__ preds,
    const float* __restrict__ tgt,
    const int*   __restrict__ tlen,
    float* __restrict__ out)
{
    __shared__ float    s_score[SURV_MAX];
    __shared__ unsigned s_meta[SURV_MAX];
    __shared__ int      s_hist[NBINS];
    __shared__ int      s_cnt, s_cutoff;
    __shared__ float    t_score[MAX_DET];
    __shared__ unsigned t_meta[MAX_DET];
    __shared__ float    t_box[MAX_DET][4];
    __shared__ float    t_area[MAX_DET];
    __shared__ unsigned s_mask[MAX_DET][KW];
    __shared__ unsigned s_keepw[KW];

    const int b   = blockIdx.x;
    const int tid = threadIdx.x;
    const int nt  = blockDim.x;

    for (int i = tid; i < NBINS; i += nt) s_hist[i] = g_hist[b][i];
    if (tid == 0) s_cnt = 0;
    __syncthreads();

    if (tid == 0) {
        int acc = 0, cut = 0;
        for (int i = NBINS - 1; i >= 0; --i) {
            acc += s_hist[i];
            if (acc >= MAX_DET) { cut = i; break; }
        }
        s_cutoff = cut;
    }
    __syncthreads();
    const int cutoff = s_cutoff;

    int C = g_cand_count[b];
    if (C > CAND_MAX) C = CAND_MAX;
    for (int i = tid; i < C; i += nt) {
        float sc = g_cand_score[b][i];
        if (score_bin(sc) >= cutoff) {
            int p = atomicAdd(&s_cnt, 1);
            if (p < SURV_MAX) { s_score[p] = sc; s_meta[p] = g_cand_meta[b][i]; }
        }
    }
    __syncthreads();
    int S = s_cnt; if (S > SURV_MAX) S = SURV_MAX;
    const int nval = (S < MAX_DET) ? S : MAX_DET;

    for (int i = tid; i < MAX_DET; i += nt) { t_score[i] = 0.0f; t_meta[i] = 0u; }
    __syncthreads();

    // exact stable rank (desc by score, asc by anchor on ties) == jax.lax.top_k order
    for (int i = tid; i < S; i += nt) {
        float v = s_score[i];
        unsigned me = s_meta[i];
        int an = (int)(me & 0xFFFFu);
        int r = 0;
        for (int j = 0; j < S; j++) {
            float u = s_score[j];
            int aj = (int)(s_meta[j] & 0xFFFFu);
            r += (u > v) || (u == v && aj < an);
        }
        if (r < MAX_DET) { t_score[r] = v; t_meta[r] = me; }
    }
    __syncthreads();

    // gather boxes of top detections, cxcywh -> xyxy (x2 = x1 + w to match ref)
    for (int i = tid; i < nval; i += nt) {
        int an = (int)(t_meta[i] & 0xFFFFu);
        const float* p = preds + ((size_t)b * NN + an) * PSTR;
        float cx = p[0], cy = p[1], w = p[2], h = p[3];
        float x1 = cx - 0.5f * w;
        float y1 = cy - 0.5f * h;
        float x2 = x1 + w;
        float y2 = y1 + h;
        t_box[i][0] = x1; t_box[i][1] = y1; t_box[i][2] = x2; t_box[i][3] = y2;
        t_area[i] = fmaxf(x2 - x1, 0.0f) * fmaxf(y2 - y1, 0.0f);
    }
    for (int i = tid; i < MAX_DET * KW; i += nt) ((unsigned*)s_mask)[i] = 0u;
    __syncthreads();

    // suppression bitmask: task = (i, word). No atomics.
    for (int t = tid; t < MAX_DET * KW; t += nt) {
        int i = t / KW, w = t - i * KW;
        if (i >= nval) continue;
        float x1i = t_box[i][0], y1i = t_box[i][1], x2i = t_box[i][2], y2i = t_box[i][3];
        float ai = t_area[i];
        unsigned li = t_meta[i] >> 16;
        unsigned m = 0u;
        int jbase = w << 5;
        #pragma unroll 4
        for (int k = 0; k < 32; k++) {
            int j = jbase + k;
            if (j <= i || j >= nval) continue;
            if ((t_meta[j] >> 16) != li) continue;
            float xx1 = fmaxf(x1i, t_box[j][0]);
            float yy1 = fmaxf(y1i, t_box[j][1]);
            float xx2 = fminf(x2i, t_box[j][2]);
            float yy2 = fminf(y2i, t_box[j][3]);
            float inter = fmaxf(xx2 - xx1, 0.0f) * fmaxf(yy2 - yy1, 0.0f);
            float iou = inter / (ai + t_area[j] - inter + 1e-9f);
            if (iou > NMS_THRES) m |= (1u << k);
        }
        s_mask[i][w] = m;
    }
    __syncthreads();

    // sequential greedy pass on warp 0, removed-words in registers
    if (tid < 32) {
        unsigned removed = 0u;
        for (int i = 0; i < nval; i++) {
            int w = i >> 5;
            int alive = (tid == w) ? (int)(!((removed >> (i & 31)) & 1u)) : 0;
            alive = __shfl_sync(0xFFFFFFFFu, alive, w);
            if (alive) {
                unsigned m = (tid < KW) ? s_mask[i][tid] : 0u;
                removed |= m;
            }
        }
        if (tid < KW) s_keepw[tid] = ~removed;
    }
    __syncthreads();

    // ---- outputs (float32, tree-flatten order) ----
    const int OFF_PB = 0;
    const int OFF_PS = BB * MAX_DET * 4;           // 19200
    const int OFF_PL = OFF_PS + BB * MAX_DET;      // 24000
    const int OFF_PV = OFF_PL + BB * MAX_DET;      // 28800
    const int OFF_TB = OFF_PV + BB * MAX_DET;      // 33600
    const int OFF_TS = OFF_TB + BB * M_TGT * 4;    // 36800
    const int OFF_TL = OFF_TS + BB * M_TGT;        // 37600
    const int OFF_TV = OFF_TL + BB * M_TGT;        // 38400

    for (int i = tid; i < MAX_DET; i += nt) {
        bool kp = (i < nval) && ((s_keepw[i >> 5] >> (i & 31)) & 1u);
        float* pb = out + OFF_PB + ((size_t)b * MAX_DET + i) * 4;
        pb[0] = kp ? t_box[i][0] : 0.0f;
        pb[1] = kp ? t_box[i][1] : 0.0f;
        pb[2] = kp ? t_box[i][2] : 0.0f;
        pb[3] = kp ? t_box[i][3] : 0.0f;
        out[OFF_PS + b * MAX_DET + i] = kp ? t_score[i] : 0.0f;
        out[OFF_PL + b * MAX_DET + i] = kp ? (float)(t_meta[i] >> 16) : -1.0f;
        out[OFF_PV + b * MAX_DET + i] = kp ? 1.0f : 0.0f;
    }

    // targets
    int L = tlen[b];
    for (int m = tid; m < M_TGT; m += nt) {
        const float* q = tgt + ((size_t)b * M_TGT + m) * 6;
        bool v = (m < L);
        float cx = q[0], cy = q[1], w = q[2], h = q[3], sc = q[4], lb = q[5];
        float x1 = cx - 0.5f * w;
        float y1 = cy - 0.5f * h;
        float* tb = out + OFF_TB + ((size_t)b * M_TGT + m) * 4;
        tb[0] = v ? x1 : 0.0f;
        tb[1] = v ? y1 : 0.0f;
        tb[2] = v ? (x1 + w) : 0.0f;
        tb[3] = v ? (y1 + h) : 0.0f;
        out[OFF_TS + b * M_TGT + m] = v ? sc : 0.0f;
        out[OFF_TL + b * M_TGT + m] = v ? lb : -1.0f;
        out[OFF_TV + b * M_TGT + m] = v ? 1.0f : 0.0f;
    }
}

extern "C" void kernel_launch(void* const* d_in, const int* in_sizes, int n_in,
                              void* d_out, int out_size) {
    const float* preds = (const float*)d_in[0];
    const float* tgt   = (const float*)d_in[1];
    const int*   tlen  = (const int*)d_in[2];
    float* out = (float*)d_out;

    // zero per-launch scratch via memset (graph-capturable, no extra kernel)
    void* p_cnt = nullptr;
    void* p_hist = nullptr;
    cudaGetSymbolAddress(&p_cnt,  g_cand_count);
    cudaGetSymbolAddress(&p_hist, g_hist);
    cudaMemsetAsync(p_cnt,  0, sizeof(int) * BB);
    cudaMemsetAsync(p_hist, 0, sizeof(int) * BB * NBINS);

    score_kernel<<<(BB * NN + 7) / 8, 256>>>(preds);   // 403200 warps, 8/block
    select_nms_kernel<<<BB, 512>>>(preds, tgt, tlen, out);
}